// round 4
// baseline (speedup 1.0000x reference)
#include <cuda_runtime.h>
#include <cstdint>

using ull  = unsigned long long;
using uint = unsigned int;

static constexpr int NN    = 16384;  // points per batch
static constexpr int KK    = 16;     // neighbors
static constexpr int CC    = 64;     // feature channels
static constexpr int DD    = 64;     // mlp out channels
static constexpr int WARPS = 8;      // warps per block
static constexpr int PPW   = 4;      // points per warp (grid sizing)
static constexpr float SLOPE = 0.1f;

#define FULLM 0xFFFFFFFFu
static constexpr ull ABSM = 0x7FFFFFFF7FFFFFFFULL;

// ---- packed f32x2 helpers (Blackwell FFMA2 path) ----
__device__ __forceinline__ ull pfma(ull a, ull b, ull c) {
    ull d; asm("fma.rn.f32x2 %0, %1, %2, %3;" : "=l"(d) : "l"(a), "l"(b), "l"(c)); return d;
}
__device__ __forceinline__ ull padd(ull a, ull b) {
    ull d; asm("add.rn.f32x2 %0, %1, %2;" : "=l"(d) : "l"(a), "l"(b)); return d;
}
__device__ __forceinline__ ull pmul(ull a, ull b) {
    ull d; asm("mul.rn.f32x2 %0, %1, %2;" : "=l"(d) : "l"(a), "l"(b)); return d;
}
__device__ __forceinline__ ull dup2(float x) {
    unsigned u = __float_as_uint(x);
    ull r; asm("mov.b64 %0, {%1, %1};" : "=l"(r) : "r"(u)); return r;
}
__device__ __forceinline__ ull pk2(float lo, float hi) {
    ull r; asm("mov.b64 %0, {%1, %2};" : "=l"(r)
               : "r"(__float_as_uint(lo)), "r"(__float_as_uint(hi))); return r;
}
__device__ __forceinline__ ull shflx64(ull x, int m) {
    uint lo = (uint)x, hi = (uint)(x >> 32);
    lo = __shfl_xor_sync(FULLM, lo, m);
    hi = __shfl_xor_sync(FULLM, hi, m);
    return (ull)lo | ((ull)hi << 32);
}

__global__ __launch_bounds__(WARPS * 32, 5)
void lfa_kernel(const float* __restrict__ features,
                const float* __restrict__ geom,
                const float* __restrict__ w,
                const float* __restrict__ bias,
                const long long* __restrict__ nidx,
                float* __restrict__ out,
                int npts)
{
    // geom per warp, each scalar pre-duplicated to f32x2 (4 x ull per k)
    __shared__ alignas(16) ull sg[WARPS][KK][4];

    const int lane = threadIdx.x & 31;
    const int wid  = threadIdx.x >> 5;
    const int p    = lane & 15;        // sub-lane within half
    const int half = lane >> 4;        // k-half: 0 -> k 0-7, 1 -> k 8-15

    // ---- per-warp index dtype detection ----
    // Probe first 16 values as int64: if data is really int32, an 8B read packs
    // two indices -> value out of [0,NN) w.h.p.
    long long probe = nidx[p];
    bool okp = (probe >= 0) && (probe < (long long)NN);
    unsigned bal = __ballot_sync(FULLM, okp);
    const bool is64 = ((bal & 0xFFFFu) == 0xFFFFu);

    // ---- weights: lane owns adjacent d-pair (2*lane, 2*lane+1) ----
    const float4* w4 = reinterpret_cast<const float4*>(w);
    float4 wa = w4[2 * lane], wb = w4[2 * lane + 1];
    const ull w0 = pk2(wa.x, wb.x), w1 = pk2(wa.y, wb.y);
    const ull w2 = pk2(wa.z, wb.z), w3 = pk2(wa.w, wb.w);
    const ull b2 = *reinterpret_cast<const ull*>(bias + 2 * lane);

    const ull C1 = dup2((1.0f + SLOPE) * 0.5f / (float)KK);
    const ull C2 = dup2((1.0f - SLOPE) * 0.5f / (float)KK);
    const ull CM = dup2(1.0f / (float)KK);

    const int gwarp   = blockIdx.x * WARPS + wid;
    const int nwtotal = gridDim.x * WARPS;

    // ---- prefetch first point's geom + idx (lanes 0-15) ----
    float4    gpre = make_float4(0.f, 0.f, 0.f, 0.f);
    long long ipre = 0;
    if (gwarp < npts && lane < KK) {
        gpre = reinterpret_cast<const float4*>(geom)[(size_t)gwarp * KK + lane];
        if (is64) ipre = nidx[(size_t)gwarp * KK + lane];
        else      ipre = (long long)reinterpret_cast<const int*>(nidx)[(size_t)gwarp * KK + lane];
    }

    for (int pt = gwarp; pt < npts; pt += nwtotal) {
        const int bb = pt / NN;

        // ---- stage prefetched geom (duplicated) + idx into regs/smem ----
        int idxv = 0;
        if (lane < KK) {
            ulonglong2 d0, d1;
            d0.x = dup2(gpre.x); d0.y = dup2(gpre.y);
            d1.x = dup2(gpre.z); d1.y = dup2(gpre.w);
            ulonglong2* dst = reinterpret_cast<ulonglong2*>(&sg[wid][lane][0]);
            dst[0] = d0;
            dst[1] = d1;
            idxv = (int)ipre;
        }
        __syncwarp();

        // ---- prefetch next point while this one computes ----
        const int ptn = pt + nwtotal;
        if (ptn < npts && lane < KK) {
            gpre = reinterpret_cast<const float4*>(geom)[(size_t)ptn * KK + lane];
            if (is64) ipre = nidx[(size_t)ptn * KK + lane];
            else      ipre = (long long)reinterpret_cast<const int*>(nidx)[(size_t)ptn * KK + lane];
        }

        // ---- gather: half-split, 8 x LDG.128 (lane owns channels 4p..4p+3) ----
        const int r0 = __shfl_sync(FULLM, idxv, 0 + 8 * half);
        const int r1 = __shfl_sync(FULLM, idxv, 1 + 8 * half);
        const int r2 = __shfl_sync(FULLM, idxv, 2 + 8 * half);
        const int r3 = __shfl_sync(FULLM, idxv, 3 + 8 * half);
        const int r4 = __shfl_sync(FULLM, idxv, 4 + 8 * half);
        const int r5 = __shfl_sync(FULLM, idxv, 5 + 8 * half);
        const int r6 = __shfl_sync(FULLM, idxv, 6 + 8 * half);
        const int r7 = __shfl_sync(FULLM, idxv, 7 + 8 * half);
        const float* fb = features + (size_t)bb * NN * CC + 4 * p;
        ulonglong2 v0 = *reinterpret_cast<const ulonglong2*>(fb + (size_t)r0 * CC);
        ulonglong2 v1 = *reinterpret_cast<const ulonglong2*>(fb + (size_t)r1 * CC);
        ulonglong2 v2 = *reinterpret_cast<const ulonglong2*>(fb + (size_t)r2 * CC);
        ulonglong2 v3 = *reinterpret_cast<const ulonglong2*>(fb + (size_t)r3 * CC);
        ulonglong2 v4 = *reinterpret_cast<const ulonglong2*>(fb + (size_t)r4 * CC);
        ulonglong2 v5 = *reinterpret_cast<const ulonglong2*>(fb + (size_t)r5 * CC);
        ulonglong2 v6 = *reinterpret_cast<const ulonglong2*>(fb + (size_t)r6 * CC);
        ulonglong2 v7 = *reinterpret_cast<const ulonglong2*>(fb + (size_t)r7 * CC);

        // ---- geom MLP over all 16 k while gather loads are in flight ----
        // mean_k lrelu(x) = c1*sum(x) + c2*sum(|x|)   (slope 0.1)
        ull xs = 0ULL, xa = 0ULL;
#pragma unroll
        for (int k = 0; k < KK; k++) {
            const ulonglong2* gk = reinterpret_cast<const ulonglong2*>(&sg[wid][k][0]);
            ulonglong2 ga = gk[0];        // LDS.128 broadcast
            ulonglong2 gb = gk[1];
            ull x = pfma(gb.y, w3, pfma(gb.x, w2, pfma(ga.y, w1, pfma(ga.x, w0, b2))));
            xs = padd(xs, x);
            xa = padd(xa, x & ABSM);
        }
        const ull t = pfma(xs, C1, pmul(xa, C2));

        // ---- gather mean: tree-sum 8 rows, then k-half butterfly ----
        ull ac0 = padd(padd(v0.x, v1.x), padd(v2.x, v3.x));
        ull ac1 = padd(padd(v0.y, v1.y), padd(v2.y, v3.y));
        ac0 = padd(ac0, padd(padd(v4.x, v5.x), padd(v6.x, v7.x)));
        ac1 = padd(ac1, padd(padd(v4.y, v5.y), padd(v6.y, v7.y)));
        ac0 = padd(ac0, shflx64(ac0, 16));
        ac1 = padd(ac1, shflx64(ac1, 16));

        // ---- stores ----
        float* op = out + (size_t)pt * (DD + CC);
        *reinterpret_cast<ull*>(op + 2 * lane) = t;     // STG.64, channels 0..63
        if (half == 0) {                                 // STG.128, channels 64..127
            ulonglong2 g2;
            g2.x = pmul(ac0, CM);
            g2.y = pmul(ac1, CM);
            *reinterpret_cast<ulonglong2*>(op + DD + 4 * p) = g2;
        }
    }
}

extern "C" void kernel_launch(void* const* d_in, const int* in_sizes, int n_in,
                              void* d_out, int out_size)
{
    const float*     features = (const float*)d_in[0];
    const float*     geom     = (const float*)d_in[1];
    const float*     w        = (const float*)d_in[2];
    const float*     b        = (const float*)d_in[3];
    const long long* nidx     = (const long long*)d_in[4];

    const int npts = in_sizes[1] / (KK * 4);             // B*N from geom
    int blocks = (npts + WARPS * PPW - 1) / (WARPS * PPW);
    if (blocks < 1) blocks = 1;

    lfa_kernel<<<blocks, WARPS * 32>>>(features, geom, w, b, nidx, (float*)d_out, npts);
}

// round 5
// speedup vs baseline: 1.0156x; 1.0156x over previous
#include <cuda_runtime.h>
#include <cstdint>

using ull  = unsigned long long;
using uint = unsigned int;

static constexpr int NN    = 16384;  // points per batch
static constexpr int KK    = 16;     // neighbors
static constexpr int CC    = 64;     // feature channels
static constexpr int DD    = 64;     // mlp out channels
static constexpr int WARPS = 8;      // warps per block
static constexpr int BLOCKS = 148 * 5; // one full wave at occupancy 5
static constexpr float SLOPE = 0.1f;

#define FULLM 0xFFFFFFFFu
static constexpr ull ABSM = 0x7FFFFFFF7FFFFFFFULL;

// ---- packed f32x2 helpers (Blackwell FFMA2 path) ----
__device__ __forceinline__ ull pfma(ull a, ull b, ull c) {
    ull d; asm("fma.rn.f32x2 %0, %1, %2, %3;" : "=l"(d) : "l"(a), "l"(b), "l"(c)); return d;
}
__device__ __forceinline__ ull padd(ull a, ull b) {
    ull d; asm("add.rn.f32x2 %0, %1, %2;" : "=l"(d) : "l"(a), "l"(b)); return d;
}
__device__ __forceinline__ ull pmul(ull a, ull b) {
    ull d; asm("mul.rn.f32x2 %0, %1, %2;" : "=l"(d) : "l"(a), "l"(b)); return d;
}
__device__ __forceinline__ ull dup2(float x) {
    unsigned u = __float_as_uint(x);
    ull r; asm("mov.b64 %0, {%1, %1};" : "=l"(r) : "r"(u)); return r;
}
__device__ __forceinline__ ull pk2(float lo, float hi) {
    ull r; asm("mov.b64 %0, {%1, %2};" : "=l"(r)
               : "r"(__float_as_uint(lo)), "r"(__float_as_uint(hi))); return r;
}
__device__ __forceinline__ ull shflx64(ull x, int m) {
    uint lo = (uint)x, hi = (uint)(x >> 32);
    lo = __shfl_xor_sync(FULLM, lo, m);
    hi = __shfl_xor_sync(FULLM, hi, m);
    return (ull)lo | ((ull)hi << 32);
}

__global__ __launch_bounds__(WARPS * 32, 5)
void lfa_kernel(const float* __restrict__ features,
                const float* __restrict__ geom,
                const float* __restrict__ w,
                const float* __restrict__ bias,
                const long long* __restrict__ nidx,
                float* __restrict__ out,
                int npts)
{
    __shared__ alignas(16) float4 sg[WARPS][KK];   // raw geom per warp

    const int lane = threadIdx.x & 31;
    const int wid  = threadIdx.x >> 5;
    const int p    = lane & 15;        // sub-lane within half
    const int half = lane >> 4;        // k-half: 0 -> k 0-7, 1 -> k 8-15

    // ---- per-warp index dtype detection ----
    // Probe first 16 values as int64: if data is really int32, an 8B read packs
    // two indices -> value out of [0,NN) w.h.p.
    long long probe = nidx[p];
    bool okp = (probe >= 0) && (probe < (long long)NN);
    unsigned bal = __ballot_sync(FULLM, okp);
    const bool is64 = ((bal & 0xFFFFu) == 0xFFFFu);

    // ---- weights: lane owns d-pairs A=(2p, 2p+1), B=(2p+32, 2p+33) ----
    const float4* w4 = reinterpret_cast<const float4*>(w);
    float4 wa = w4[2 * p],      wb = w4[2 * p + 1];
    float4 wc = w4[2 * p + 32], wd = w4[2 * p + 33];
    const ull wA0 = pk2(wa.x, wb.x), wA1 = pk2(wa.y, wb.y);
    const ull wA2 = pk2(wa.z, wb.z), wA3 = pk2(wa.w, wb.w);
    const ull wB0 = pk2(wc.x, wd.x), wB1 = pk2(wc.y, wd.y);
    const ull wB2 = pk2(wc.z, wd.z), wB3 = pk2(wc.w, wd.w);
    const ull bA  = *reinterpret_cast<const ull*>(bias + 2 * p);
    const ull bB  = *reinterpret_cast<const ull*>(bias + 2 * p + 32);

    const ull C1 = dup2((1.0f + SLOPE) * 0.5f / (float)KK);
    const ull C2 = dup2((1.0f - SLOPE) * 0.5f / (float)KK);
    const ull CM = dup2(1.0f / (float)KK);

    const int gwarp   = blockIdx.x * WARPS + wid;
    const int nwtotal = BLOCKS * WARPS;

    for (int pt = gwarp; pt < npts; pt += nwtotal) {
        const int bb = pt / NN;

        // ---- stage: geom + idx (lanes 0-15) ----
        int idxv = 0;
        if (lane < KK) {
            sg[wid][lane] = reinterpret_cast<const float4*>(geom)[(size_t)pt * KK + lane];
            long long v;
            if (is64) v = nidx[(size_t)pt * KK + lane];
            else      v = (long long)reinterpret_cast<const int*>(nidx)[(size_t)pt * KK + lane];
            idxv = (int)v;
        }
        __syncwarp();

        // ---- gather: half-split, 8 x LDG.128 (lane owns channels 4p..4p+3) ----
        const int r0 = __shfl_sync(FULLM, idxv, 0 + 8 * half);
        const int r1 = __shfl_sync(FULLM, idxv, 1 + 8 * half);
        const int r2 = __shfl_sync(FULLM, idxv, 2 + 8 * half);
        const int r3 = __shfl_sync(FULLM, idxv, 3 + 8 * half);
        const int r4 = __shfl_sync(FULLM, idxv, 4 + 8 * half);
        const int r5 = __shfl_sync(FULLM, idxv, 5 + 8 * half);
        const int r6 = __shfl_sync(FULLM, idxv, 6 + 8 * half);
        const int r7 = __shfl_sync(FULLM, idxv, 7 + 8 * half);
        const float* fb = features + (size_t)bb * NN * CC + 4 * p;
        ulonglong2 v0 = *reinterpret_cast<const ulonglong2*>(fb + (size_t)r0 * CC);
        ulonglong2 v1 = *reinterpret_cast<const ulonglong2*>(fb + (size_t)r1 * CC);
        ulonglong2 v2 = *reinterpret_cast<const ulonglong2*>(fb + (size_t)r2 * CC);
        ulonglong2 v3 = *reinterpret_cast<const ulonglong2*>(fb + (size_t)r3 * CC);
        ulonglong2 v4 = *reinterpret_cast<const ulonglong2*>(fb + (size_t)r4 * CC);
        ulonglong2 v5 = *reinterpret_cast<const ulonglong2*>(fb + (size_t)r5 * CC);
        ulonglong2 v6 = *reinterpret_cast<const ulonglong2*>(fb + (size_t)r6 * CC);
        ulonglong2 v7 = *reinterpret_cast<const ulonglong2*>(fb + (size_t)r7 * CC);

        // ---- geom MLP while gather loads are in flight ----
        // half-split over k: this lane covers k = 8*half .. 8*half+7,
        // for d-pairs A and B; dup-to-f32x2 happens in registers (ALU pipe).
        ull sA = 0ULL, aA = 0ULL, sB = 0ULL, aB = 0ULL;
#pragma unroll
        for (int i = 0; i < 8; i++) {
            float4 gk = sg[wid][i + 8 * half];     // LDS.128, broadcast per half
            ull g0 = dup2(gk.x), g1 = dup2(gk.y), g2 = dup2(gk.z), g3 = dup2(gk.w);
            ull xA = pfma(g3, wA3, pfma(g2, wA2, pfma(g1, wA1, pfma(g0, wA0, bA))));
            ull xB = pfma(g3, wB3, pfma(g2, wB2, pfma(g1, wB1, pfma(g0, wB0, bB))));
            sA = padd(sA, xA);  aA = padd(aA, xA & ABSM);
            sB = padd(sB, xB);  aB = padd(aB, xB & ABSM);
        }
        // combine k-halves (partner lane l^16 has same d-pairs, other k-half)
        sA = padd(sA, shflx64(sA, 16));
        aA = padd(aA, shflx64(aA, 16));
        sB = padd(sB, shflx64(sB, 16));
        aB = padd(aB, shflx64(aB, 16));

        // mean_k lrelu(x) = c1*sum(x) + c2*sum(|x|)   (slope 0.1)
        const ull tA = pfma(sA, C1, pmul(aA, C2));
        const ull tB = pfma(sB, C1, pmul(aB, C2));

        // ---- gather mean: tree-sum 8 rows, then k-half butterfly ----
        ull ac0 = padd(padd(v0.x, v1.x), padd(v2.x, v3.x));
        ull ac1 = padd(padd(v0.y, v1.y), padd(v2.y, v3.y));
        ac0 = padd(ac0, padd(padd(v4.x, v5.x), padd(v6.x, v7.x)));
        ac1 = padd(ac1, padd(padd(v4.y, v5.y), padd(v6.y, v7.y)));
        ac0 = padd(ac0, shflx64(ac0, 16));
        ac1 = padd(ac1, shflx64(ac1, 16));

        // ---- stores: every lane does 2 x STG.64, all contiguous ----
        float* op = out + (size_t)pt * (DD + CC);
        // t: half 0 stores pair (2p,2p+1), half 1 stores (2p+32,2p+33)
        *reinterpret_cast<ull*>(op + 2 * p + 32 * half) = half ? tB : tA;
        // gather: half 0 stores channels (4p,4p+1), half 1 stores (4p+2,4p+3)
        *reinterpret_cast<ull*>(op + DD + 4 * p + 2 * half)
            = pmul(half ? ac1 : ac0, CM);
    }
}

extern "C" void kernel_launch(void* const* d_in, const int* in_sizes, int n_in,
                              void* d_out, int out_size)
{
    const float*     features = (const float*)d_in[0];
    const float*     geom     = (const float*)d_in[1];
    const float*     w        = (const float*)d_in[2];
    const float*     b        = (const float*)d_in[3];
    const long long* nidx     = (const long long*)d_in[4];

    const int npts = in_sizes[1] / (KK * 4);             // B*N from geom

    lfa_kernel<<<BLOCKS, WARPS * 32>>>(features, geom, w, b, nidx, (float*)d_out, npts);
}